// round 2
// baseline (speedup 1.0000x reference)
#include <cuda_runtime.h>
#include <math.h>

// Fused single kernel:
//  - thread 0 of each block builds the 4x4 SE3 exp-map matrix (rows 0..2 as
//    (R_i0, R_i1, R_i2, t_i); row 3 is [0,0,0,1]) into shared memory.
//  - all threads then stream-transform two float4 columns each.
//
// x and out are [4, N] row-major; processed as float4 columns (n4 = N/4).
// Column range is split into two halves: thread i handles columns i and
// i + half, so both streams stay perfectly coalesced.
__global__ void __launch_bounds__(256)
se3_fused(const float4* __restrict__ x, float4* __restrict__ out,
          const float* __restrict__ w, const float* __restrict__ v,
          const float* __restrict__ theta_p, int n4, int half) {
    __shared__ float4 sM[3];

    if (threadIdx.x == 0) {
        const float wx = w[0], wy = w[1], wz = w[2];
        const float vx = v[0], vy = v[1], vz = v[2];
        const float th = theta_p[0];
        const float s = sinf(th);
        const float c = cosf(th);
        const float a = 1.0f - c;      // matches jax fp32: (1 - cos)
        const float b = th - s;        // matches jax fp32: (theta - sin)

        float K[3][3] = { {0.f, -wz,  wy},
                          { wz, 0.f, -wx},
                          {-wy,  wx, 0.f} };
        float KK[3][3];
        #pragma unroll
        for (int i = 0; i < 3; i++)
            #pragma unroll
            for (int j = 0; j < 3; j++)
                KK[i][j] = K[i][0]*K[0][j] + K[i][1]*K[1][j] + K[i][2]*K[2][j];

        float R[3][3], V[3][3];
        #pragma unroll
        for (int i = 0; i < 3; i++)
            #pragma unroll
            for (int j = 0; j < 3; j++) {
                const float I = (i == j) ? 1.0f : 0.0f;
                R[i][j] = I + s * K[i][j] + a * KK[i][j];
                V[i][j] = I * th + a * K[i][j] + b * KK[i][j];
            }

        float t0 = V[0][0]*vx + V[0][1]*vy + V[0][2]*vz;
        float t1 = V[1][0]*vx + V[1][1]*vy + V[1][2]*vz;
        float t2 = V[2][0]*vx + V[2][1]*vy + V[2][2]*vz;

        sM[0] = make_float4(R[0][0], R[0][1], R[0][2], t0);
        sM[1] = make_float4(R[1][0], R[1][1], R[1][2], t1);
        sM[2] = make_float4(R[2][0], R[2][1], R[2][2], t2);
    }
    __syncthreads();

    const int i = blockIdx.x * blockDim.x + threadIdx.x;
    if (i >= half) return;

    const float4 m0 = sM[0];
    const float4 m1 = sM[1];
    const float4 m2 = sM[2];

    const size_t iA = (size_t)i;
    const size_t iB = (size_t)i + (size_t)half;
    const size_t s1 = (size_t)n4;

    // Front-batch all 8 loads (MLP_p1 = 8), streaming eviction policy.
    const float4 a0 = __ldcs(&x[iA]);
    const float4 a1 = __ldcs(&x[iA + s1]);
    const float4 a2 = __ldcs(&x[iA + 2*s1]);
    const float4 a3 = __ldcs(&x[iA + 3*s1]);
    const float4 b0 = __ldcs(&x[iB]);
    const float4 b1 = __ldcs(&x[iB + s1]);
    const float4 b2 = __ldcs(&x[iB + 2*s1]);
    const float4 b3 = __ldcs(&x[iB + 3*s1]);

    float4 ra0, ra1, ra2, rb0, rb1, rb2;

    ra0.x = m0.x*a0.x + m0.y*a1.x + m0.z*a2.x + m0.w*a3.x;
    ra0.y = m0.x*a0.y + m0.y*a1.y + m0.z*a2.y + m0.w*a3.y;
    ra0.z = m0.x*a0.z + m0.y*a1.z + m0.z*a2.z + m0.w*a3.z;
    ra0.w = m0.x*a0.w + m0.y*a1.w + m0.z*a2.w + m0.w*a3.w;

    ra1.x = m1.x*a0.x + m1.y*a1.x + m1.z*a2.x + m1.w*a3.x;
    ra1.y = m1.x*a0.y + m1.y*a1.y + m1.z*a2.y + m1.w*a3.y;
    ra1.z = m1.x*a0.z + m1.y*a1.z + m1.z*a2.z + m1.w*a3.z;
    ra1.w = m1.x*a0.w + m1.y*a1.w + m1.z*a2.w + m1.w*a3.w;

    ra2.x = m2.x*a0.x + m2.y*a1.x + m2.z*a2.x + m2.w*a3.x;
    ra2.y = m2.x*a0.y + m2.y*a1.y + m2.z*a2.y + m2.w*a3.y;
    ra2.z = m2.x*a0.z + m2.y*a1.z + m2.z*a2.z + m2.w*a3.z;
    ra2.w = m2.x*a0.w + m2.y*a1.w + m2.z*a2.w + m2.w*a3.w;

    rb0.x = m0.x*b0.x + m0.y*b1.x + m0.z*b2.x + m0.w*b3.x;
    rb0.y = m0.x*b0.y + m0.y*b1.y + m0.z*b2.y + m0.w*b3.y;
    rb0.z = m0.x*b0.z + m0.y*b1.z + m0.z*b2.z + m0.w*b3.z;
    rb0.w = m0.x*b0.w + m0.y*b1.w + m0.z*b2.w + m0.w*b3.w;

    rb1.x = m1.x*b0.x + m1.y*b1.x + m1.z*b2.x + m1.w*b3.x;
    rb1.y = m1.x*b0.y + m1.y*b1.y + m1.z*b2.y + m1.w*b3.y;
    rb1.z = m1.x*b0.z + m1.y*b1.z + m1.z*b2.z + m1.w*b3.z;
    rb1.w = m1.x*b0.w + m1.y*b1.w + m1.z*b2.w + m1.w*b3.w;

    rb2.x = m2.x*b0.x + m2.y*b1.x + m2.z*b2.x + m2.w*b3.x;
    rb2.y = m2.x*b0.y + m2.y*b1.y + m2.z*b2.y + m2.w*b3.y;
    rb2.z = m2.x*b0.z + m2.y*b1.z + m2.z*b2.z + m2.w*b3.z;
    rb2.w = m2.x*b0.w + m2.y*b1.w + m2.z*b2.w + m2.w*b3.w;

    __stcs(&out[iA],        ra0);
    __stcs(&out[iA + s1],   ra1);
    __stcs(&out[iA + 2*s1], ra2);
    __stcs(&out[iA + 3*s1], a3);   // bottom row of M is [0,0,0,1]
    __stcs(&out[iB],        rb0);
    __stcs(&out[iB + s1],   rb1);
    __stcs(&out[iB + 2*s1], rb2);
    __stcs(&out[iB + 3*s1], b3);
}

extern "C" void kernel_launch(void* const* d_in, const int* in_sizes, int n_in,
                              void* d_out, int out_size) {
    const float* x     = (const float*)d_in[0];   // [4, N]
    const float* w     = (const float*)d_in[1];   // [3]
    const float* v     = (const float*)d_in[2];   // [3]
    const float* theta = (const float*)d_in[3];   // scalar

    const int N    = in_sizes[0] / 4;   // columns
    const int n4   = N / 4;             // float4 columns per row
    const int half = n4 / 2;            // two columns per thread

    const int threads = 256;
    const int blocks  = (half + threads - 1) / threads;
    se3_fused<<<blocks, threads>>>((const float4*)x, (float4*)d_out,
                                   w, v, theta, n4, half);
}

// round 3
// speedup vs baseline: 1.0192x; 1.0192x over previous
#include <cuda_runtime.h>
#include <math.h>

// Single fused kernel. Per block:
//   1. every thread issues its 4 streaming x-loads FIRST (independent of M)
//   2. thread 0 builds the 4x4 SE3 exp-map matrix into shared memory
//      (rows 0..2 as (R_i0, R_i1, R_i2, t_i); row 3 is [0,0,0,1])
//   3. __syncthreads, then FMAs + stores.
// The loads are in flight while the matrix is built, so the barrier costs
// ~nothing on top of the unavoidable load latency.
//
// x and out are [4, N] row-major; processed as float4 columns (n4 = N/4).
__global__ void __launch_bounds__(256)
se3_fused(const float4* __restrict__ x, float4* __restrict__ out,
          const float* __restrict__ w, const float* __restrict__ v,
          const float* __restrict__ theta_p, int n4) {
    __shared__ float4 sM[3];

    const int i = blockIdx.x * blockDim.x + threadIdx.x;
    const bool active = (i < n4);
    const size_t s1 = (size_t)n4;

    // ---- 1. front-batch the streaming loads (before the barrier) ----
    float4 x0, x1, x2, x3;
    if (active) {
        x0 = x[i];
        x1 = x[i + s1];
        x2 = x[i + 2*s1];
        x3 = x[i + 3*s1];
    }

    // ---- 2. matrix build (thread 0 only), overlapped with the loads ----
    if (threadIdx.x == 0) {
        const float wx = w[0], wy = w[1], wz = w[2];
        const float vx = v[0], vy = v[1], vz = v[2];
        const float th = theta_p[0];
        const float s = sinf(th);
        const float c = cosf(th);
        const float a = 1.0f - c;      // matches jax fp32: (1 - cos)
        const float b = th - s;        // matches jax fp32: (theta - sin)

        float K[3][3] = { {0.f, -wz,  wy},
                          { wz, 0.f, -wx},
                          {-wy,  wx, 0.f} };
        float KK[3][3];
        #pragma unroll
        for (int r = 0; r < 3; r++)
            #pragma unroll
            for (int j = 0; j < 3; j++)
                KK[r][j] = K[r][0]*K[0][j] + K[r][1]*K[1][j] + K[r][2]*K[2][j];

        float R[3][3], V[3][3];
        #pragma unroll
        for (int r = 0; r < 3; r++)
            #pragma unroll
            for (int j = 0; j < 3; j++) {
                const float I = (r == j) ? 1.0f : 0.0f;
                R[r][j] = I + s * K[r][j] + a * KK[r][j];
                V[r][j] = I * th + a * K[r][j] + b * KK[r][j];
            }

        float t0 = V[0][0]*vx + V[0][1]*vy + V[0][2]*vz;
        float t1 = V[1][0]*vx + V[1][1]*vy + V[1][2]*vz;
        float t2 = V[2][0]*vx + V[2][1]*vy + V[2][2]*vz;

        sM[0] = make_float4(R[0][0], R[0][1], R[0][2], t0);
        sM[1] = make_float4(R[1][0], R[1][1], R[1][2], t1);
        sM[2] = make_float4(R[2][0], R[2][1], R[2][2], t2);
    }
    __syncthreads();

    if (!active) return;

    // ---- 3. transform + store ----
    const float4 m0 = sM[0];
    const float4 m1 = sM[1];
    const float4 m2 = sM[2];

    float4 r0, r1, r2;
    r0.x = m0.x*x0.x + m0.y*x1.x + m0.z*x2.x + m0.w*x3.x;
    r0.y = m0.x*x0.y + m0.y*x1.y + m0.z*x2.y + m0.w*x3.y;
    r0.z = m0.x*x0.z + m0.y*x1.z + m0.z*x2.z + m0.w*x3.z;
    r0.w = m0.x*x0.w + m0.y*x1.w + m0.z*x2.w + m0.w*x3.w;

    r1.x = m1.x*x0.x + m1.y*x1.x + m1.z*x2.x + m1.w*x3.x;
    r1.y = m1.x*x0.y + m1.y*x1.y + m1.z*x2.y + m1.w*x3.y;
    r1.z = m1.x*x0.z + m1.y*x1.z + m1.z*x2.z + m1.w*x3.z;
    r1.w = m1.x*x0.w + m1.y*x1.w + m1.z*x2.w + m1.w*x3.w;

    r2.x = m2.x*x0.x + m2.y*x1.x + m2.z*x2.x + m2.w*x3.x;
    r2.y = m2.x*x0.y + m2.y*x1.y + m2.z*x2.y + m2.w*x3.y;
    r2.z = m2.x*x0.z + m2.y*x1.z + m2.z*x2.z + m2.w*x3.z;
    r2.w = m2.x*x0.w + m2.y*x1.w + m2.z*x2.w + m2.w*x3.w;

    __stcs(&out[i],        r0);
    __stcs(&out[i + s1],   r1);
    __stcs(&out[i + 2*s1], r2);
    __stcs(&out[i + 3*s1], x3);   // bottom row of M is [0,0,0,1]
}

extern "C" void kernel_launch(void* const* d_in, const int* in_sizes, int n_in,
                              void* d_out, int out_size) {
    const float* x     = (const float*)d_in[0];   // [4, N]
    const float* w     = (const float*)d_in[1];   // [3]
    const float* v     = (const float*)d_in[2];   // [3]
    const float* theta = (const float*)d_in[3];   // scalar

    const int N  = in_sizes[0] / 4;   // columns
    const int n4 = N / 4;             // float4 columns per row

    const int threads = 256;
    const int blocks  = (n4 + threads - 1) / threads;
    se3_fused<<<blocks, threads>>>((const float4*)x, (float4*)d_out,
                                   w, v, theta, n4);
}